// round 16
// baseline (speedup 1.0000x reference)
#include <cuda_runtime.h>
#include <cuda_bf16.h>
#include <cstdint>
#include <cstddef>

#define NB 64
#define NH 12
#define NP 197
#define ND 64
#define TOPK 10
#define NSLOT 7
#define FULLMASK 0xffffffffu
#define LSLOTS 12    // per-warp per-lane slots: S e2..e6 in 0..4, sentinels 5..6, T e2..e6 in 11..7
#define KSC 1.44269504f   // 1/ln2 (folded so pop decode is a bare ex2.approx)
#define KOF 23.083f       // shift keeps key floats positive -> bit order == value order

// Persistent device state (statically initialized; last block resets -> replay-safe)
__device__ double g_acc = 0.0;
__device__ unsigned g_done = 0;

__device__ __forceinline__ float ex2f(float x) {
    float r; asm("ex2.approx.f32 %0, %1;" : "=f"(r) : "f"(x)); return r;
}
// descending compare-exchange (2x IMNMX.U32)
__device__ __forceinline__ void ceu(unsigned& a, unsigned& b) {
    unsigned mx = a > b ? a : b;
    unsigned mn = a > b ? b : a;
    a = mx; b = mn;
}
// Batcher odd-even mergesort for 8 with element 7 = const-min -> 16-CE sort-7.
__device__ __forceinline__ void sort7(unsigned* s) {
    ceu(s[0],s[1]); ceu(s[2],s[3]); ceu(s[4],s[5]);
    ceu(s[0],s[2]); ceu(s[1],s[3]); ceu(s[4],s[6]);
    ceu(s[1],s[2]); ceu(s[5],s[6]);
    ceu(s[0],s[4]); ceu(s[1],s[5]); ceu(s[2],s[6]);
    ceu(s[2],s[4]); ceu(s[3],s[5]);
    ceu(s[1],s[2]); ceu(s[3],s[4]); ceu(s[5],s[6]);
}

// Pad -15.9 -> key float ~0.15 > 0, below any real logit's key; never tops REDUX.
__device__ __forceinline__ void load_row(float* y, const float* __restrict__ row,
                                         int lane) {
#pragma unroll
    for (int k = 0; k < 6; ++k) y[k] = row[k * 32 + lane];
    y[6] = (lane < NP - 192) ? row[192 + lane] : -15.9f;
}

// unpack bf16x2 (lo = d even, hi = d odd) via shift trick -- no CVT pipe.
__device__ __forceinline__ float2 bf2_unpack(unsigned w) {
    return make_float2(__uint_as_float(w << 16),
                       __uint_as_float(w & 0xFFFF0000u));
}

__global__ void __launch_bounds__(256, 3)
hintop_main(const float* __restrict__ att_s, const float* __restrict__ att_t,
            const float* __restrict__ v_s,   const float* __restrict__ v_t,
            float* __restrict__ out) {
    extern __shared__ unsigned smem_u[];
    unsigned* vsS = smem_u;                              // NP*ND/2 bf16x2 words each
    unsigned* vsT = smem_u + NP * ND / 2;
    unsigned* lists = smem_u + NP * ND;                  // 8 * LSLOTS * 32 words

    const int bh   = blockIdx.x;                         // (b*H + h), 0..767
    const int warp = threadIdx.x >> 5;
    const int lane = threadIdx.x & 31;

    {   // fill both v tiles as packed bf16x2 (halves smem -> 3 CTAs/SM)
        const float4* a4 = reinterpret_cast<const float4*>(v_s + (size_t)bh * NP * ND);
        const float4* b4 = reinterpret_cast<const float4*>(v_t + (size_t)bh * NP * ND);
        uint2* s2 = reinterpret_cast<uint2*>(vsS);
        uint2* t2 = reinterpret_cast<uint2*>(vsT);
        for (int i = threadIdx.x; i < NP * ND / 4; i += 256) {
            float4 a = a4[i];
            float4 b = b4[i];
            __nv_bfloat162 a0 = __floats2bfloat162_rn(a.x, a.y);
            __nv_bfloat162 a1 = __floats2bfloat162_rn(a.z, a.w);
            __nv_bfloat162 b0 = __floats2bfloat162_rn(b.x, b.y);
            __nv_bfloat162 b1 = __floats2bfloat162_rn(b.z, b.w);
            s2[i] = make_uint2(*(unsigned*)&a0, *(unsigned*)&a1);
            t2[i] = make_uint2(*(unsigned*)&b0, *(unsigned*)&b1);
        }
    }
    // per-warp per-lane list base; zero the two shared sentinel slots once
    const int lb = warp * (LSLOTS * 32) + lane;
    lists[lb + 5 * 32] = 0u;
    lists[lb + 6 * 32] = 0u;
    __syncthreads();

    const float* aS = att_s + (size_t)bh * NP * NP;
    const float* aT = att_t + (size_t)bh * NP * NP;
    // u32 element i*32+lane holds v[i][2*lane .. 2*lane+1] as bf16x2
    const unsigned* __restrict__ v2S = vsS + lane;
    const unsigned* __restrict__ v2T = vsT + lane;

    float lsum = 0.f;
    int p = warp;
    float cS[NSLOT], cT[NSLOT];
    load_row(cS, aS + (size_t)p * NP, lane);
    load_row(cT, aT + (size_t)p * NP, lane);

    while (p < NP) {
        const int pn = p + 8;

        // ---- keys: FFMA folds 1/ln2; positive => bit order == value order
        unsigned sS[NSLOT], sT[NSLOT];
#pragma unroll
        for (int k = 0; k < NSLOT; ++k) {
            unsigned idx = (unsigned)(k * 32 + lane);
            sS[k] = (__float_as_uint(fmaf(cS[k], KSC, KOF)) & 0xFFFFFF00u) | idx;
            sT[k] = (__float_as_uint(fmaf(cT[k], KSC, KOF)) & 0xFFFFFF00u) | idx;
        }
        sort7(sS);
        sort7(sT);

        // ---- spill entries 2..6; S ascending slots 0..4, T descending 11..7
#pragma unroll
        for (int j = 0; j < 5; ++j) {
            lists[lb + j * 32] = sS[2 + j];
            lists[lb + (11 - j) * 32] = sT[2 + j];
        }

        // ---- cS/cT are DEAD after key build: prefetch next rows directly into
        //      them (no double buffer). Clamped; tail iteration discarded.
        {
            int pl = pn < NP - 1 ? pn : NP - 1;
            load_row(cS, aS + (size_t)pl * NP, lane);
            load_row(cT, aT + (size_t)pl * NP, lane);
        }

        // ---- pop top-10 per chain; two independent REDUX chains for ILP
        unsigned candS = sS[0], nextS = sS[1];
        unsigned candT = sT[0], nextT = sT[1];
        int lpS = lb;                 // reads slots 0..4 then sentinels 5,6
        int lpT = lb + 11 * 32;       // reads slots 11..7 then sentinels 6,5
        float2 accS = make_float2(0.f, 0.f), accT = make_float2(0.f, 0.f);
        float wsS = 0.f, wsT = 0.f;
#pragma unroll
        for (int it = 0; it < TOPK; ++it) {
            unsigned wmS = __reduce_max_sync(FULLMASK, candS);
            unsigned wmT = __reduce_max_sync(FULLMASK, candT);

            if (it < TOPK - 1) {
                bool oS = (candS == wmS);         // unique keys -> one owner
                candS = oS ? nextS : candS;
                if (oS) { nextS = lists[lpS]; lpS += 32; }   // refill off-chain
                bool oT = (candT == wmT);
                candT = oT ? nextT : candT;
                if (oT) { nextT = lists[lpT]; lpT -= 32; }
            }

            // w = 2^(key bits as float): one MUFU.EX2, no mask, no FMUL.
            // idx-bit noise <= 3.4e-4 rel; KOF and base-2 cancel in normalizer.
            float wS = ex2f(__uint_as_float(wmS));
            float wT = ex2f(__uint_as_float(wmT));
            unsigned iS = wmS & 0xFFu;
            unsigned iT = wmT & 0xFFu;
            float2 vvS = bf2_unpack(v2S[iS * 32]);
            float2 vvT = bf2_unpack(v2T[iT * 32]);
            accS.x = fmaf(wS, vvS.x, accS.x);
            accS.y = fmaf(wS, vvS.y, accS.y);
            wsS += wS;
            accT.x = fmaf(wT, vvT.x, accT.x);
            accT.y = fmaf(wT, vvT.y, accT.y);
            wsT += wT;
        }

        float invS = __fdividef(1.0f, wsS);
        float invT = __fdividef(1.0f, wsT);
        float dx = accS.x * invS - accT.x * invT;
        float dy = accS.y * invS - accT.y * invT;
        lsum = fmaf(dx, dx, lsum);
        lsum = fmaf(dy, dy, lsum);

        p = pn;
    }

    // warp reduce -> block reduce -> one double atomic; last block finalizes.
#pragma unroll
    for (int off = 16; off; off >>= 1) lsum += __shfl_xor_sync(FULLMASK, lsum, off);

    __shared__ float wsum_sh[8];
    if (lane == 0) wsum_sh[warp] = lsum;
    __syncthreads();
    if (threadIdx.x == 0) {
        float t = 0.f;
#pragma unroll
        for (int w = 0; w < 8; ++w) t += wsum_sh[w];
        atomicAdd(&g_acc, (double)t);
        __threadfence();
        unsigned ticket = atomicAdd(&g_done, 1);
        if (ticket == (unsigned)(gridDim.x - 1)) {
            __threadfence();
            double total = atomicAdd(&g_acc, 0.0);
            out[0] = (float)(total / (double)((size_t)NB * NH * NP * ND));
            g_acc = 0.0;                                 // reset for graph replay
            g_done = 0;
            __threadfence();
        }
    }
}

extern "C" void kernel_launch(void* const* d_in, const int* in_sizes, int n_in,
                              void* d_out, int out_size) {
    const float* att_s = (const float*)d_in[0];
    const float* att_t = (const float*)d_in[1];
    const float* v_s   = (const float*)d_in[2];
    const float* v_t   = (const float*)d_in[3];

    // 50,432 (two bf16 v tiles) + 12,288 (lists) = 62,720 B -> 3 CTAs/SM
    const int smem_bytes = NP * ND * 4 + 8 * LSLOTS * 32 * 4;
    cudaFuncSetAttribute(hintop_main, cudaFuncAttributeMaxDynamicSharedMemorySize,
                         smem_bytes);

    hintop_main<<<NB * NH, 256, smem_bytes>>>(att_s, att_t, v_s, v_t, (float*)d_out);
}

// round 17
// speedup vs baseline: 1.0537x; 1.0537x over previous
#include <cuda_runtime.h>
#include <cuda_bf16.h>
#include <cstdint>
#include <cstddef>

#define NB 64
#define NH 12
#define NP 197
#define ND 64
#define TOPK 10
#define NSLOT 7
#define FULLMASK 0xffffffffu
#define LSLOTS 12    // per-warp per-lane slots: S e2..e6 in 0..4, sentinels 5..6, T e2..e6 in 11..7
#define KSC 1.44269504f   // 1/ln2 (folded so pop decode is a bare ex2.approx)
#define KOF 23.083f       // shift keeps key floats positive -> bit order == value order

// Persistent device state (statically initialized; last block resets -> replay-safe)
__device__ double g_acc = 0.0;
__device__ unsigned g_done = 0;

__device__ __forceinline__ float ex2f(float x) {
    float r; asm("ex2.approx.f32 %0, %1;" : "=f"(r) : "f"(x)); return r;
}
// broadcast f32 -> packed bf16x2 in ONE cvt instruction
__device__ __forceinline__ __nv_bfloat162 bcast_bf2(float w) {
    unsigned r;
    asm("cvt.rn.bf16x2.f32 %0, %1, %2;" : "=r"(r) : "f"(w), "f"(w));
    return *reinterpret_cast<__nv_bfloat162*>(&r);
}
// exact bf16 -> f32 via bit shift (no CVT pipe)
__device__ __forceinline__ float2 bf2_unpack(__nv_bfloat162 v) {
    unsigned w = *reinterpret_cast<unsigned*>(&v);
    return make_float2(__uint_as_float(w << 16),
                       __uint_as_float(w & 0xFFFF0000u));
}
// descending compare-exchange (2x IMNMX.U32)
__device__ __forceinline__ void ceu(unsigned& a, unsigned& b) {
    unsigned mx = a > b ? a : b;
    unsigned mn = a > b ? b : a;
    a = mx; b = mn;
}
// Batcher odd-even mergesort for 8 with element 7 = const-min -> 16-CE sort-7.
__device__ __forceinline__ void sort7(unsigned* s) {
    ceu(s[0],s[1]); ceu(s[2],s[3]); ceu(s[4],s[5]);
    ceu(s[0],s[2]); ceu(s[1],s[3]); ceu(s[4],s[6]);
    ceu(s[1],s[2]); ceu(s[5],s[6]);
    ceu(s[0],s[4]); ceu(s[1],s[5]); ceu(s[2],s[6]);
    ceu(s[2],s[4]); ceu(s[3],s[5]);
    ceu(s[1],s[2]); ceu(s[3],s[4]); ceu(s[5],s[6]);
}

// Pad -15.9 -> key float ~0.15 > 0, below any real logit's key; never tops REDUX.
__device__ __forceinline__ void load_row(float* y, const float* __restrict__ row,
                                         int lane) {
#pragma unroll
    for (int k = 0; k < 6; ++k) y[k] = row[k * 32 + lane];
    y[6] = (lane < NP - 192) ? row[192 + lane] : -15.9f;
}

__global__ void __launch_bounds__(256, 3)
hintop_main(const float* __restrict__ att_s, const float* __restrict__ att_t,
            const float* __restrict__ v_s,   const float* __restrict__ v_t,
            float* __restrict__ out) {
    extern __shared__ unsigned smem_u[];
    unsigned* vsS = smem_u;                              // NP*ND/2 bf16x2 words each
    unsigned* vsT = smem_u + NP * ND / 2;
    unsigned* lists = smem_u + NP * ND;                  // 8 * LSLOTS * 32 words

    const int bh   = blockIdx.x;                         // (b*H + h), 0..767
    const int warp = threadIdx.x >> 5;
    const int lane = threadIdx.x & 31;

    {   // fill both v tiles as packed bf16x2 (halves smem -> 3 CTAs/SM)
        const float4* a4 = reinterpret_cast<const float4*>(v_s + (size_t)bh * NP * ND);
        const float4* b4 = reinterpret_cast<const float4*>(v_t + (size_t)bh * NP * ND);
        uint2* s2 = reinterpret_cast<uint2*>(vsS);
        uint2* t2 = reinterpret_cast<uint2*>(vsT);
        for (int i = threadIdx.x; i < NP * ND / 4; i += 256) {
            float4 a = a4[i];
            float4 b = b4[i];
            __nv_bfloat162 a0 = __floats2bfloat162_rn(a.x, a.y);
            __nv_bfloat162 a1 = __floats2bfloat162_rn(a.z, a.w);
            __nv_bfloat162 b0 = __floats2bfloat162_rn(b.x, b.y);
            __nv_bfloat162 b1 = __floats2bfloat162_rn(b.z, b.w);
            s2[i] = make_uint2(*(unsigned*)&a0, *(unsigned*)&a1);
            t2[i] = make_uint2(*(unsigned*)&b0, *(unsigned*)&b1);
        }
    }
    // per-warp per-lane list base; zero the two shared sentinel slots once
    const int lb = warp * (LSLOTS * 32) + lane;
    lists[lb + 5 * 32] = 0u;
    lists[lb + 6 * 32] = 0u;
    __syncthreads();

    const float* aS = att_s + (size_t)bh * NP * NP;
    const float* aT = att_t + (size_t)bh * NP * NP;
    // bf16x2 element i*32+lane holds v[i][2*lane .. 2*lane+1]
    const __nv_bfloat162* __restrict__ v2S =
        reinterpret_cast<const __nv_bfloat162*>(vsS) + lane;
    const __nv_bfloat162* __restrict__ v2T =
        reinterpret_cast<const __nv_bfloat162*>(vsT) + lane;

    float lsum = 0.f;
    int p = warp;
    float cS[NSLOT], cT[NSLOT];
    load_row(cS, aS + (size_t)p * NP, lane);
    load_row(cT, aT + (size_t)p * NP, lane);

    while (p < NP) {
        const int pn = p + 8;

        // ---- keys: FFMA folds 1/ln2; positive => bit order == value order
        unsigned sS[NSLOT], sT[NSLOT];
#pragma unroll
        for (int k = 0; k < NSLOT; ++k) {
            unsigned idx = (unsigned)(k * 32 + lane);
            sS[k] = (__float_as_uint(fmaf(cS[k], KSC, KOF)) & 0xFFFFFF00u) | idx;
            sT[k] = (__float_as_uint(fmaf(cT[k], KSC, KOF)) & 0xFFFFFF00u) | idx;
        }
        sort7(sS);
        sort7(sT);

        // ---- spill entries 2..6; S ascending slots 0..4, T descending 11..7
#pragma unroll
        for (int j = 0; j < 5; ++j) {
            lists[lb + j * 32] = sS[2 + j];
            lists[lb + (11 - j) * 32] = sT[2 + j];
        }

        // ---- cS/cT are DEAD after key build: prefetch next rows directly into
        //      them (no double buffer). Clamped; tail iteration discarded.
        {
            int pl = pn < NP - 1 ? pn : NP - 1;
            load_row(cS, aS + (size_t)pl * NP, lane);
            load_row(cT, aT + (size_t)pl * NP, lane);
        }

        // ---- pop top-10 per chain; two independent REDUX chains for ILP.
        //      Accumulate in packed bf16x2: 1 HFMA2 replaces unpack+2 FFMA.
        unsigned candS = sS[0], nextS = sS[1];
        unsigned candT = sT[0], nextT = sT[1];
        int lpS = lb;                 // reads slots 0..4 then sentinels 5,6
        int lpT = lb + 11 * 32;       // reads slots 11..7 then sentinels 6,5
        __nv_bfloat162 accS = __float2bfloat162_rn(0.f);
        __nv_bfloat162 accT = __float2bfloat162_rn(0.f);
        float wsS = 0.f, wsT = 0.f;
#pragma unroll
        for (int it = 0; it < TOPK; ++it) {
            unsigned wmS = __reduce_max_sync(FULLMASK, candS);
            unsigned wmT = __reduce_max_sync(FULLMASK, candT);

            if (it < TOPK - 1) {
                bool oS = (candS == wmS);         // unique keys -> one owner
                candS = oS ? nextS : candS;
                if (oS) { nextS = lists[lpS]; lpS += 32; }   // refill off-chain
                bool oT = (candT == wmT);
                candT = oT ? nextT : candT;
                if (oT) { nextT = lists[lpT]; lpT -= 32; }
            }

            // w = 2^(key bits as float): one MUFU.EX2; KOF/base-2 cancel in
            // the normalizer. idx-bit noise <= 3.4e-4 rel on w.
            float wS = ex2f(__uint_as_float(wmS));
            float wT = ex2f(__uint_as_float(wmT));
            unsigned iS = wmS & 0xFFu;
            unsigned iT = wmT & 0xFFu;
            accS = __hfma2(bcast_bf2(wS), v2S[iS * 32], accS);
            accT = __hfma2(bcast_bf2(wT), v2T[iT * 32], accT);
            wsS += wS;
            wsT += wT;
        }

        float2 oS2 = bf2_unpack(accS);           // exact bf16->f32 (shift)
        float2 oT2 = bf2_unpack(accT);
        float invS = __fdividef(1.0f, wsS);
        float invT = __fdividef(1.0f, wsT);
        float dx = oS2.x * invS - oT2.x * invT;
        float dy = oS2.y * invS - oT2.y * invT;
        lsum = fmaf(dx, dx, lsum);
        lsum = fmaf(dy, dy, lsum);

        p = pn;
    }

    // warp reduce -> block reduce -> one double atomic; last block finalizes.
#pragma unroll
    for (int off = 16; off; off >>= 1) lsum += __shfl_xor_sync(FULLMASK, lsum, off);

    __shared__ float wsum_sh[8];
    if (lane == 0) wsum_sh[warp] = lsum;
    __syncthreads();
    if (threadIdx.x == 0) {
        float t = 0.f;
#pragma unroll
        for (int w = 0; w < 8; ++w) t += wsum_sh[w];
        atomicAdd(&g_acc, (double)t);
        __threadfence();
        unsigned ticket = atomicAdd(&g_done, 1);
        if (ticket == (unsigned)(gridDim.x - 1)) {
            __threadfence();
            double total = atomicAdd(&g_acc, 0.0);
            out[0] = (float)(total / (double)((size_t)NB * NH * NP * ND));
            g_acc = 0.0;                                 // reset for graph replay
            g_done = 0;
            __threadfence();
        }
    }
}

extern "C" void kernel_launch(void* const* d_in, const int* in_sizes, int n_in,
                              void* d_out, int out_size) {
    const float* att_s = (const float*)d_in[0];
    const float* att_t = (const float*)d_in[1];
    const float* v_s   = (const float*)d_in[2];
    const float* v_t   = (const float*)d_in[3];

    // 50,432 (two bf16 v tiles) + 12,288 (lists) = 62,720 B -> 3 CTAs/SM
    const int smem_bytes = NP * ND * 4 + 8 * LSLOTS * 32 * 4;
    cudaFuncSetAttribute(hintop_main, cudaFuncAttributeMaxDynamicSharedMemorySize,
                         smem_bytes);

    hintop_main<<<NB * NH, 256, smem_bytes>>>(att_s, att_t, v_s, v_t, (float*)d_out);
}